// round 6
// baseline (speedup 1.0000x reference)
#include <cuda_runtime.h>
#include <math.h>

#define Bsz 256
#define Ssz 50
#define Csz 40
#define Dsz 256
#define TDIFF 1000

#define LSTM_GX 16
#define LSTM_GY 8
#define LSTM_NBLK (LSTM_GX*LSTM_GY)

typedef unsigned long long ull;

// f32x2 helpers (sm_103a packed fp32 — ptxas never auto-emits; inline PTX only)
__device__ __forceinline__ ull fdup(float x) {
    ull r; asm("mov.b64 %0, {%1, %1};" : "=l"(r) : "f"(x)); return r;
}
#define FMA2(d, a, b) asm("fma.rn.f32x2 %0, %1, %2, %0;" : "+l"(d) : "l"(a), "l"(b))
#define ADD2(d, a)    asm("add.rn.f32x2 %0, %0, %1;"     : "+l"(d) : "l"(a))

union UPair { ull u; float2 f; };

// ---------------- scratch ----------------
__device__ float g_x[Bsz*Ssz*Dsz];
__device__ float g_Gih[Bsz*Ssz*4*Dsz];      // x@Wih^T + (bih+bhh)
__device__ float g_hbuf[2][Bsz*Dsz];
__device__ float g_rnn[Bsz*Ssz*Dsz];
__device__ float g_w[Bsz*Ssz*Dsz];
__device__ float g_featE[Bsz*64];
__device__ float g_featW[Bsz*Ssz*64];
__device__ float g_aligned[Bsz*Ssz*Dsz];
__device__ float g_pre[Bsz*Ssz*Dsz];
__device__ float g_alpha[Bsz];
__device__ float g_WdiffT[Dsz*Dsz];
__device__ float g_bsum[4*Dsz];

__device__ unsigned g_barCnt;
__device__ volatile unsigned g_barGen;

// ============ gemm128: C[M,N] = A[M,K]·B[N,K]^T + bias, f32x2 core ============
// 128x128 tile, 256 threads, 8x8 microtile as 8x(4 pairs). K % 16 == 0.
__global__ void __launch_bounds__(256)
gemm128(int M, int N, int K,
        const float* __restrict__ A, int lda,
        const float* __restrict__ B, int ldb,
        const float* __restrict__ bias,
        float* __restrict__ C, int ldc)
{
    __shared__ ull   As2[2][16][128];   // duplicated (a,a) pairs, [k][m]
    __shared__ float Bs [2][16][128];   // [k][n]

    const int tid = threadIdx.x;
    const int m0 = blockIdx.y * 128;
    const int n0 = blockIdx.x * 128;
    const int tx = tid & 15;            // n block of 8
    const int ty = tid >> 4;            // m block of 8
    const int r  = tid >> 2;            // 0..63 load row
    const int c4 = (tid & 3) * 4;       // k offset

    const float* Ag = A + (size_t)(m0 + r) * lda + c4;
    const float* Bg = B + (size_t)(n0 + r) * ldb + c4;

    ull acc[8][4];
    #pragma unroll
    for (int i = 0; i < 8; i++)
        #pragma unroll
        for (int p = 0; p < 4; p++) acc[i][p] = 0ull;

    // prologue: tile 0
    {
        float4 a0 = *(const float4*)(Ag);
        float4 a1 = *(const float4*)(Ag + 64 * (size_t)lda);
        float4 b0 = *(const float4*)(Bg);
        float4 b1 = *(const float4*)(Bg + 64 * (size_t)ldb);
        const float* av0 = &a0.x; const float* av1 = &a1.x;
        const float* bv0 = &b0.x; const float* bv1 = &b1.x;
        #pragma unroll
        for (int j = 0; j < 4; j++) {
            As2[0][c4+j][r]    = fdup(av0[j]);
            As2[0][c4+j][r+64] = fdup(av1[j]);
            Bs [0][c4+j][r]    = bv0[j];
            Bs [0][c4+j][r+64] = bv1[j];
        }
    }
    __syncthreads();

    const int nkb = K >> 4;
    for (int kb = 0; kb < nkb; kb++) {
        const int buf = kb & 1;
        float4 a0, a1, b0, b1;
        const bool pf = (kb + 1 < nkb);
        if (pf) {
            int k0 = (kb + 1) * 16;
            a0 = *(const float4*)(Ag + k0);
            a1 = *(const float4*)(Ag + 64 * (size_t)lda + k0);
            b0 = *(const float4*)(Bg + k0);
            b1 = *(const float4*)(Bg + 64 * (size_t)ldb + k0);
        }
        #pragma unroll
        for (int k = 0; k < 16; k++) {
            const ull* ap = &As2[buf][k][ty * 8];
            ulonglong2 a01 = *(const ulonglong2*)(ap + 0);
            ulonglong2 a23 = *(const ulonglong2*)(ap + 2);
            ulonglong2 a45 = *(const ulonglong2*)(ap + 4);
            ulonglong2 a67 = *(const ulonglong2*)(ap + 6);
            const ull* bp = (const ull*)&Bs[buf][k][tx * 8];
            ulonglong2 b01 = *(const ulonglong2*)(bp + 0);
            ulonglong2 b23 = *(const ulonglong2*)(bp + 2);
            ull av[8] = {a01.x, a01.y, a23.x, a23.y, a45.x, a45.y, a67.x, a67.y};
            ull bv[4] = {b01.x, b01.y, b23.x, b23.y};
            #pragma unroll
            for (int i = 0; i < 8; i++) {
                FMA2(acc[i][0], av[i], bv[0]);
                FMA2(acc[i][1], av[i], bv[1]);
                FMA2(acc[i][2], av[i], bv[2]);
                FMA2(acc[i][3], av[i], bv[3]);
            }
        }
        if (pf) {
            __syncthreads();
            const float* av0 = &a0.x; const float* av1 = &a1.x;
            const float* bv0 = &b0.x; const float* bv1 = &b1.x;
            #pragma unroll
            for (int j = 0; j < 4; j++) {
                As2[buf^1][c4+j][r]    = fdup(av0[j]);
                As2[buf^1][c4+j][r+64] = fdup(av1[j]);
                Bs [buf^1][c4+j][r]    = bv0[j];
                Bs [buf^1][c4+j][r+64] = bv1[j];
            }
            __syncthreads();
        }
    }

    // epilogue: + bias (packed), store
    ull bb[4];
    {
        const ull* bp2 = (const ull*)(bias + n0 + tx * 8);
        bb[0] = bp2[0]; bb[1] = bp2[1]; bb[2] = bp2[2]; bb[3] = bp2[3];
    }
    #pragma unroll
    for (int i = 0; i < 8; i++) {
        int row = m0 + ty * 8 + i;
        float2* crow = (float2*)(C + (size_t)row * ldc + n0 + tx * 8);
        #pragma unroll
        for (int p = 0; p < 4; p++) {
            ADD2(acc[i][p], bb[p]);
            UPair u; u.u = acc[i][p];
            crow[p] = u.f;
        }
    }
}

// ============ small-N GEMM (kept for N=64 attention features) ============
__global__ void gemm_nt(int M, int N, int K,
                        const float* __restrict__ A, int lda,
                        const float* __restrict__ B, int ldb,
                        const float* __restrict__ bias,
                        float* __restrict__ C, int ldc)
{
    __shared__ float As[16][68];
    __shared__ float Bsh[16][68];
    const int tid = threadIdx.x;
    const int m0 = blockIdx.y * 64;
    const int n0 = blockIdx.x * 64;
    const int tx = tid & 15;
    const int ty = tid >> 4;
    const int lr = tid >> 2;
    const int lc = (tid & 3) * 4;

    float acc[4][4] = {};
    for (int k0 = 0; k0 < K; k0 += 16) {
        float4 a4 = *(const float4*)(A + (size_t)(m0 + lr) * lda + k0 + lc);
        float4 b4 = *(const float4*)(B + (size_t)(n0 + lr) * ldb + k0 + lc);
        As[lc+0][lr] = a4.x; As[lc+1][lr] = a4.y; As[lc+2][lr] = a4.z; As[lc+3][lr] = a4.w;
        Bsh[lc+0][lr] = b4.x; Bsh[lc+1][lr] = b4.y; Bsh[lc+2][lr] = b4.z; Bsh[lc+3][lr] = b4.w;
        __syncthreads();
        #pragma unroll
        for (int k = 0; k < 16; k++) {
            float a[4], b[4];
            #pragma unroll
            for (int i = 0; i < 4; i++) a[i] = As[k][ty*4 + i];
            #pragma unroll
            for (int j = 0; j < 4; j++) b[j] = Bsh[k][tx*4 + j];
            #pragma unroll
            for (int i = 0; i < 4; i++)
                #pragma unroll
                for (int j = 0; j < 4; j++)
                    acc[i][j] = fmaf(a[i], b[j], acc[i][j]);
        }
        __syncthreads();
    }
    #pragma unroll
    for (int i = 0; i < 4; i++) {
        int row = m0 + ty*4 + i;
        #pragma unroll
        for (int j = 0; j < 4; j++) {
            int col = n0 + tx*4 + j;
            float v = acc[i][j];
            if (bias) v += bias[col];
            C[(size_t)row * ldc + col] = v;
        }
    }
}

// ---------------- embedding gather-sum ----------------
__global__ void embed_kernel(const int* __restrict__ seqs,
                             const float* __restrict__ emb)
{
    int bs = blockIdx.x;
    int d  = threadIdx.x;
    __shared__ int idx[Csz];
    if (threadIdx.x < Csz) idx[threadIdx.x] = seqs[bs * Csz + threadIdx.x];
    __syncthreads();
    float acc = 0.f;
    #pragma unroll 8
    for (int c = 0; c < Csz; c++)
        acc += __ldg(emb + (size_t)idx[c] * Dsz + d);
    g_x[(size_t)bs * Dsz + d] = acc;
}

// ---------------- alpha lookup ----------------
__global__ void alpha_kernel(const int* __restrict__ t)
{
    __shared__ float tab[TDIFF];
    if (threadIdx.x == 0) {
        float a = 1.f;
        for (int i = 0; i < TDIFF; i++) {
            float beta = 1e-4f + (0.02f - 1e-4f) * (float)i / (float)(TDIFF - 1);
            a *= (1.f - beta);
            tab[i] = a;
        }
    }
    __syncthreads();
    if (threadIdx.x < Bsz) g_alpha[threadIdx.x] = tab[t[threadIdx.x]];
}

// ---------------- bias sum ----------------
__global__ void bsum_kernel(const float* __restrict__ bih,
                            const float* __restrict__ bhh)
{
    int i = blockIdx.x * 256 + threadIdx.x;
    g_bsum[i] = bih[i] + bhh[i];
}

// ---------------- fused persistent LSTM (f32x2 core) ----------------
__device__ __forceinline__ float sigf(float x) { return 1.f / (1.f + expf(-x)); }

__device__ __forceinline__ void gridBarrier()
{
    __syncthreads();
    if (threadIdx.x == 0) {
        __threadfence();
        unsigned gen = g_barGen;
        __threadfence();
        if (atomicAdd(&g_barCnt, 1u) == LSTM_NBLK - 1) {
            g_barCnt = 0;
            __threadfence();
            g_barGen = gen + 1;
        } else {
            while (g_barGen == gen) __nanosleep(64);
        }
        __threadfence();
    }
    __syncthreads();
}

// shared: Bs u32[256][68] (gate-interleaved Whh; pairs (i,f),(g,o) natural)
//       + As2 ull[256][34] (duplicated h pairs)
#define LSTM_SMEM (256*68*8)

__global__ void __launch_bounds__(128, 1)
lstm_fused(const float* __restrict__ Whh)
{
    extern __shared__ float sh[];
    float* Bsf = sh;                     // [k][j*4+g] scalar view
    ull*   Bsp = (ull*)sh;               // [k][j*2+p] pair view (stride 34)
    ull*   As2 = (ull*)(sh + 256*68);    // [k][m] dup pairs (stride 34)

    const int tid = threadIdx.x;
    const int nb  = blockIdx.x;
    const int mb  = blockIdx.y;
    const int m0  = mb * 32;
    const int tx  = tid & 15;
    const int ty  = tid >> 4;
    const int d   = nb * 16 + tx;

    // one-time Whh slice load (gate-interleaved)
    {
        int rr = tid >> 1;
        int g = rr & 3, j = rr >> 2;
        const float* src = Whh + (size_t)(g * 256 + nb * 16 + j) * 256;
        for (int q = (tid & 1); q < 64; q += 2) {
            float4 v = *(const float4*)(src + q * 4);
            Bsf[(q*4+0)*68 + rr] = v.x;
            Bsf[(q*4+1)*68 + rr] = v.y;
            Bsf[(q*4+2)*68 + rr] = v.z;
            Bsf[(q*4+3)*68 + rr] = v.w;
        }
    }
    float cst[4] = {0.f, 0.f, 0.f, 0.f};
    __syncthreads();

    for (int t = 0; t < Ssz; t++) {
        // prefetch Gih epilogue operands early (hides L2 latency behind GEMM)
        float pg[4][4];
        #pragma unroll
        for (int i = 0; i < 4; i++) {
            size_t gb = ((size_t)(m0 + ty*4 + i) * Ssz + t) * 1024 + d;
            pg[i][0] = g_Gih[gb];
            pg[i][1] = g_Gih[gb + 256];
            pg[i][2] = g_Gih[gb + 512];
            pg[i][3] = g_Gih[gb + 768];
        }

        ull acc[4][2] = {{0ull,0ull},{0ull,0ull},{0ull,0ull},{0ull,0ull}};
        if (t > 0) {
            const float* hsrc = g_hbuf[(t + 1) & 1] + (size_t)m0 * Dsz;
            int rr = tid >> 2;
            const float* arow = hsrc + (size_t)rr * Dsz;
            for (int q = (tid & 3); q < 64; q += 4) {
                float4 v = *(const float4*)(arow + q * 4);
                As2[(q*4+0)*34 + rr] = fdup(v.x);
                As2[(q*4+1)*34 + rr] = fdup(v.y);
                As2[(q*4+2)*34 + rr] = fdup(v.z);
                As2[(q*4+3)*34 + rr] = fdup(v.w);
            }
            __syncthreads();
            #pragma unroll 8
            for (int k = 0; k < 256; k++) {
                const ull* ap = As2 + k*34 + ty*4;
                ulonglong2 a01 = *(const ulonglong2*)(ap + 0);
                ulonglong2 a23 = *(const ulonglong2*)(ap + 2);
                const ull* bp = Bsp + k*34 + tx*2;
                ulonglong2 bv = *(const ulonglong2*)bp;
                FMA2(acc[0][0], a01.x, bv.x); FMA2(acc[0][1], a01.x, bv.y);
                FMA2(acc[1][0], a01.y, bv.x); FMA2(acc[1][1], a01.y, bv.y);
                FMA2(acc[2][0], a23.x, bv.x); FMA2(acc[2][1], a23.x, bv.y);
                FMA2(acc[3][0], a23.y, bv.x); FMA2(acc[3][1], a23.y, bv.y);
            }
        }
        float* hdst = g_hbuf[t & 1];
        #pragma unroll
        for (int i = 0; i < 4; i++) {
            int b = m0 + ty * 4 + i;
            UPair u0, u1; u0.u = acc[i][0]; u1.u = acc[i][1];
            float gi = u0.f.x + pg[i][0];
            float gf = u0.f.y + pg[i][1];
            float gg = u1.f.x + pg[i][2];
            float go = u1.f.y + pg[i][3];
            float iv = sigf(gi), fv = sigf(gf);
            float gv = tanhf(gg), ov = sigf(go);
            cst[i] = fv * cst[i] + iv * gv;
            float h = ov * tanhf(cst[i]);
            hdst[(size_t)b * Dsz + d] = h;
            g_rnn[((size_t)b * Ssz + t) * Dsz + d] = h;
        }
        gridBarrier();
    }
}

// ---------------- attention + aligned + diffusion prep (fused) ----------------
__global__ void attn_diff(const float* __restrict__ W2,
                          const float* __restrict__ b2,
                          const float* __restrict__ noise,
                          const float* __restrict__ temb,
                          const int* __restrict__ tdi)
{
    int s = blockIdx.x;
    int b = blockIdx.y;
    int tid = threadIdx.x;
    const float* ek = g_x + (size_t)b * Ssz * Dsz;
    size_t orow = ((size_t)b * Ssz + s) * Dsz;

    float av;
    if (s == 0) {
        av = ek[tid];
    } else {
        __shared__ float s0[64], s1[64];
        __shared__ float a0s, a1s;
        int sm1 = s - 1;
        if (tid < 64) {
            float f = tanhf(g_featE[b*64 + tid] + g_featW[((size_t)b*Ssz + sm1)*64 + tid]);
            s0[tid] = f * W2[tid];
            s1[tid] = f * W2[64 + tid];
        }
        __syncthreads();
        if (tid == 0) {
            float l0 = b2[0], l1 = b2[1];
            for (int j = 0; j < 64; j++) { l0 += s0[j]; l1 += s1[j]; }
            float m = fmaxf(l0, l1);
            float e0 = expf(l0 - m), e1 = expf(l1 - m);
            float inv = 1.f / (e0 + e1);
            a0s = e0 * inv; a1s = e1 * inv;
        }
        __syncthreads();
        float wv = g_w[((size_t)b * Ssz + sm1) * Dsz + tid];
        av = a0s * ek[tid] + a1s * wv;
    }
    g_aligned[orow + tid] = av;
    float al = g_alpha[b];
    float sa = sqrtf(al), sn = sqrtf(1.f - al);
    g_pre[orow + tid] = av * sa + noise[orow + tid] * sn
                      + temb[(size_t)tdi[b] * Dsz + tid];
}

__global__ void transpose_wdiff(const float* __restrict__ Wdiff)
{
    int n = blockIdx.x, k = threadIdx.x;
    g_WdiffT[n * Dsz + k] = __ldg(Wdiff + k * Dsz + n);
}

// ---------------- fused max-pool + final projections ----------------
__global__ void poolfinal(const float* __restrict__ noise,
                          const float* __restrict__ pn,
                          const float* __restrict__ Wout,
                          const float* __restrict__ bout,
                          float* __restrict__ out)
{
    int b = blockIdx.x, d = threadIdx.x;
    float xm = -INFINITY, gm = -INFINITY;
    for (int s = 0; s < Ssz; s++) {
        size_t i = ((size_t)b * Ssz + s) * Dsz + d;
        xm = fmaxf(xm, g_x[i]);
        float gv = g_aligned[i] + noise[i] - pn[i];
        gm = fmaxf(gm, gv);
    }
    __shared__ float4 red[256];
    red[d] = make_float4(xm * Wout[d], xm * Wout[Dsz + d],
                         gm * Wout[d], gm * Wout[Dsz + d]);
    __syncthreads();
    for (int off = 128; off > 0; off >>= 1) {
        if (d < off) {
            float4 a = red[d], c = red[d + off];
            red[d] = make_float4(a.x + c.x, a.y + c.y, a.z + c.z, a.w + c.w);
        }
        __syncthreads();
    }
    if (d == 0) {
        float4 r = red[0];
        out[b*2 + 0]         = r.x + bout[0];
        out[b*2 + 1]         = r.y + bout[1];
        out[2*Bsz + b*2 + 0] = r.z + bout[0];
        out[2*Bsz + b*2 + 1] = r.w + bout[1];
    }
}

// ---------------- host ----------------
static float* sym(const void* s)
{
    void* p = nullptr;
    cudaGetSymbolAddress(&p, s);
    return (float*)p;
}

extern "C" void kernel_launch(void* const* d_in, const int* in_sizes, int n_in,
                              void* d_out, int out_size)
{
    const int*   seqs   = (const int*)  d_in[0];
    const int*   tdiff  = (const int*)  d_in[5];
    const float* noise  = (const float*)d_in[6];
    const float* emb    = (const float*)d_in[7];
    const float* Wih    = (const float*)d_in[8];
    const float* Whh    = (const float*)d_in[9];
    const float* bih    = (const float*)d_in[10];
    const float* bhh    = (const float*)d_in[11];
    const float* Whk    = (const float*)d_in[12];
    const float* bhk    = (const float*)d_in[13];
    const float* W1     = (const float*)d_in[14];
    const float* b1     = (const float*)d_in[15];
    const float* W2     = (const float*)d_in[16];
    const float* b2     = (const float*)d_in[17];
    const float* Wdiff  = (const float*)d_in[18];
    const float* bdiff  = (const float*)d_in[19];
    const float* temb   = (const float*)d_in[20];
    const float* Wout   = (const float*)d_in[21];
    const float* bout   = (const float*)d_in[22];
    float* out = (float*)d_out;

    float* p_x    = sym(g_x);
    float* p_Gih  = sym(g_Gih);
    float* p_rnn  = sym(g_rnn);
    float* p_w    = sym(g_w);
    float* p_fE   = sym(g_featE);
    float* p_fW   = sym(g_featW);
    float* p_pre  = sym(g_pre);
    float* p_WdT  = sym(g_WdiffT);
    float* p_bsum = sym(g_bsum);

    static bool attr_done = false;
    if (!attr_done) {
        cudaFuncSetAttribute(lstm_fused,
                             cudaFuncAttributeMaxDynamicSharedMemorySize,
                             LSTM_SMEM);
        attr_done = true;
    }

    const int MD = 4 * Dsz;            // 1024
    float* pn_out = out + 4 * Bsz;
    float* nn_out = out + 4 * Bsz + (size_t)Bsz * Ssz * Dsz;

    alpha_kernel<<<1, 256>>>(tdiff);
    bsum_kernel<<<4, 256>>>(bih, bhh);
    embed_kernel<<<Bsz * Ssz, Dsz>>>(seqs, emb);

    // Gih = x @ Wih^T + (bih+bhh)   (12800 x 1024 x 256)
    gemm128<<<dim3(MD/128, (Bsz*Ssz)/128), 256>>>(Bsz*Ssz, MD, Dsz,
        p_x, Dsz, Wih, Dsz, p_bsum, p_Gih, MD);

    // fused persistent LSTM
    lstm_fused<<<dim3(LSTM_GX, LSTM_GY), 128, LSTM_SMEM>>>(Whh);

    // w = rnn @ Whk^T + bhk   (12800 x 256 x 256)
    gemm128<<<dim3(Dsz/128, (Bsz*Ssz)/128), 256>>>(Bsz*Ssz, Dsz, Dsz,
        p_rnn, Dsz, Whk, Dsz, bhk, p_w, Dsz);

    // attention features (N=64)
    gemm_nt<<<dim3(1, Bsz/64), 256>>>(Bsz, 64, Dsz,
        p_x, Ssz * Dsz, W1, 2 * Dsz, b1, p_fE, 64);
    gemm_nt<<<dim3(1, (Bsz*Ssz)/64), 256>>>(Bsz*Ssz, 64, Dsz,
        p_w, Dsz, W1 + Dsz, 2 * Dsz, nullptr, p_fW, 64);

    // attention softmax + aligned + diffusion prep (fused)
    attn_diff<<<dim3(Ssz, Bsz), Dsz>>>(W2, b2, noise, temb, tdiff);

    // predicted_noise = pre @ Wdiff + bdiff
    transpose_wdiff<<<Dsz, Dsz>>>(Wdiff);
    gemm128<<<dim3(Dsz/128, (Bsz*Ssz)/128), 256>>>(Bsz*Ssz, Dsz, Dsz,
        p_pre, Dsz, p_WdT, Dsz, bdiff, pn_out, Dsz);

    // fused pool + final
    poolfinal<<<Bsz, Dsz>>>(noise, pn_out, Wout, bout, out);

    // normal_noise passthrough
    cudaMemcpyAsync(nn_out, noise, (size_t)Bsz * Ssz * Dsz * sizeof(float),
                    cudaMemcpyDeviceToDevice);
}

// round 7
// speedup vs baseline: 1.0743x; 1.0743x over previous
#include <cuda_runtime.h>
#include <math.h>

#define Bsz 256
#define Ssz 50
#define Csz 40
#define Dsz 256
#define TDIFF 1000

#define LSTM_GX 16   // h-dim blocks (16 dims each)
#define LSTM_GY 8    // batch blocks (32 rows each)

// ---------------- scratch ----------------
__device__ float g_x[Bsz*Ssz*Dsz];
__device__ float g_Gih[Bsz*Ssz*4*Dsz];      // x@Wih^T + (bih+bhh)
__device__ float g_rnn[Bsz*Ssz*Dsz];
__device__ float g_w[Bsz*Ssz*Dsz];
__device__ float g_featE[Bsz*64];
__device__ float g_featW[Bsz*Ssz*64];
__device__ float g_aligned[Bsz*Ssz*Dsz];
__device__ float g_pre[Bsz*Ssz*Dsz];
__device__ float g_alpha[Bsz];
__device__ float g_WdiffT[Dsz*Dsz];
__device__ float g_bsum[4*Dsz];

__device__ unsigned g_barCnt[LSTM_GY];
__device__ volatile unsigned g_barGen[LSTM_GY];

// ============ 64x64 NT GEMM (proven 85%-of-FFMA-peak config) ============
__global__ void gemm_nt(int M, int N, int K,
                        const float* __restrict__ A, int lda,
                        const float* __restrict__ B, int ldb,
                        const float* __restrict__ bias,
                        float* __restrict__ C, int ldc)
{
    __shared__ float As[16][68];
    __shared__ float Bsh[16][68];
    const int tid = threadIdx.x;
    const int m0 = blockIdx.y * 64;
    const int n0 = blockIdx.x * 64;
    const int tx = tid & 15;
    const int ty = tid >> 4;
    const int lr = tid >> 2;
    const int lc = (tid & 3) * 4;

    float acc[4][4] = {};
    for (int k0 = 0; k0 < K; k0 += 16) {
        float4 a4 = *(const float4*)(A + (size_t)(m0 + lr) * lda + k0 + lc);
        float4 b4 = *(const float4*)(B + (size_t)(n0 + lr) * ldb + k0 + lc);
        As[lc+0][lr] = a4.x; As[lc+1][lr] = a4.y; As[lc+2][lr] = a4.z; As[lc+3][lr] = a4.w;
        Bsh[lc+0][lr] = b4.x; Bsh[lc+1][lr] = b4.y; Bsh[lc+2][lr] = b4.z; Bsh[lc+3][lr] = b4.w;
        __syncthreads();
        #pragma unroll
        for (int k = 0; k < 16; k++) {
            float a[4], b[4];
            #pragma unroll
            for (int i = 0; i < 4; i++) a[i] = As[k][ty*4 + i];
            #pragma unroll
            for (int j = 0; j < 4; j++) b[j] = Bsh[k][tx*4 + j];
            #pragma unroll
            for (int i = 0; i < 4; i++)
                #pragma unroll
                for (int j = 0; j < 4; j++)
                    acc[i][j] = fmaf(a[i], b[j], acc[i][j]);
        }
        __syncthreads();
    }
    #pragma unroll
    for (int i = 0; i < 4; i++) {
        int row = m0 + ty*4 + i;
        #pragma unroll
        for (int j = 0; j < 4; j++) {
            int col = n0 + tx*4 + j;
            float v = acc[i][j];
            if (bias) v += bias[col];
            C[(size_t)row * ldc + col] = v;
        }
    }
}

// ---------------- embedding gather-sum ----------------
__global__ void embed_kernel(const int* __restrict__ seqs,
                             const float* __restrict__ emb)
{
    int bs = blockIdx.x;
    int d  = threadIdx.x;
    __shared__ int idx[Csz];
    if (threadIdx.x < Csz) idx[threadIdx.x] = seqs[bs * Csz + threadIdx.x];
    __syncthreads();
    float acc = 0.f;
    #pragma unroll 8
    for (int c = 0; c < Csz; c++)
        acc += __ldg(emb + (size_t)idx[c] * Dsz + d);
    g_x[(size_t)bs * Dsz + d] = acc;
}

// ---------------- alpha lookup ----------------
__global__ void alpha_kernel(const int* __restrict__ t)
{
    __shared__ float tab[TDIFF];
    if (threadIdx.x == 0) {
        float a = 1.f;
        for (int i = 0; i < TDIFF; i++) {
            float beta = 1e-4f + (0.02f - 1e-4f) * (float)i / (float)(TDIFF - 1);
            a *= (1.f - beta);
            tab[i] = a;
        }
    }
    __syncthreads();
    if (threadIdx.x < Bsz) g_alpha[threadIdx.x] = tab[t[threadIdx.x]];
}

// ---------------- bias sum ----------------
__global__ void bsum_kernel(const float* __restrict__ bih,
                            const float* __restrict__ bhh)
{
    int i = blockIdx.x * 256 + threadIdx.x;
    g_bsum[i] = bih[i] + bhh[i];
}

// ---------------- fused persistent LSTM ----------------
__device__ __forceinline__ float sigf(float x) { return 1.f / (1.f + expf(-x)); }

// 16-CTA group barrier (CTAs sharing mb only)
__device__ __forceinline__ void groupBarrier(int grp)
{
    __syncthreads();
    if (threadIdx.x == 0) {
        __threadfence();
        unsigned gen = g_barGen[grp];
        __threadfence();
        if (atomicAdd(&g_barCnt[grp], 1u) == LSTM_GX - 1) {
            g_barCnt[grp] = 0;
            __threadfence();
            g_barGen[grp] = gen + 1;
        } else {
            while (g_barGen[grp] == gen) __nanosleep(32);
        }
        __threadfence();
    }
    __syncthreads();
}

// shared: Bs[256][68] gate-interleaved Whh (persistent) + As[256][36] h tile
#define LSTM_SMEM ((256*68 + 256*36) * (int)sizeof(float))

__global__ void __launch_bounds__(256, 1)
lstm_fused(const float* __restrict__ Whh)
{
    extern __shared__ float sh[];
    float* Bsf = sh;               // [k][j*4+g], stride 68
    float* As  = sh + 256*68;      // [k][m],     stride 36

    const int tid = threadIdx.x;
    const int nb  = blockIdx.x;    // 0..15: h-dims nb*16..+15
    const int mb  = blockIdx.y;    // 0..7 : batch rows mb*32..+31
    const int m0  = mb * 32;
    const int tx  = tid & 15;      // h-dim
    const int ty  = tid >> 4;      // 0..15: rows m0+ty*2+{0,1}
    const int d   = nb * 16 + tx;

    // one-time Whh slice load, gate-interleaved: Bsf[k][j*4+g] = Whh[g*256+nb*16+j][k]
    {
        int r = tid >> 2;          // 0..63
        int g = r & 3, j = r >> 2;
        const float* src = Whh + (size_t)(g * 256 + nb * 16 + j) * 256;
        for (int q = (tid & 3); q < 64; q += 4) {
            float4 v = *(const float4*)(src + q * 4);
            Bsf[(q*4+0)*68 + r] = v.x;
            Bsf[(q*4+1)*68 + r] = v.y;
            Bsf[(q*4+2)*68 + r] = v.z;
            Bsf[(q*4+3)*68 + r] = v.w;
        }
    }
    float cst[2] = {0.f, 0.f};
    __syncthreads();

    for (int t = 0; t < Ssz; t++) {
        // prefetch Gih epilogue operands (in flight through staging + compute)
        float pg[2][4];
        #pragma unroll
        for (int i = 0; i < 2; i++) {
            size_t gb = ((size_t)(m0 + ty*2 + i) * Ssz + t) * 1024 + d;
            pg[i][0] = __ldg(g_Gih + gb);
            pg[i][1] = __ldg(g_Gih + gb + 256);
            pg[i][2] = __ldg(g_Gih + gb + 512);
            pg[i][3] = __ldg(g_Gih + gb + 768);
        }

        float acc[2][4] = {};
        if (t > 0) {
            // stage h tile (32 x 256) from g_rnn step t-1, transposed
            int rr = tid >> 3;     // 0..31
            const float* arow = g_rnn + ((size_t)(m0 + rr) * Ssz + (t - 1)) * Dsz;
            for (int q = (tid & 7); q < 64; q += 8) {
                float4 v = *(const float4*)(arow + q * 4);
                As[(q*4+0)*36 + rr] = v.x;
                As[(q*4+1)*36 + rr] = v.y;
                As[(q*4+2)*36 + rr] = v.z;
                As[(q*4+3)*36 + rr] = v.w;
            }
            __syncthreads();
            #pragma unroll 8
            for (int k = 0; k < 256; k++) {
                float2 a = *(const float2*)(As + k * 36 + ty * 2);
                float4 b = *(const float4*)(Bsf + k * 68 + tx * 4);
                acc[0][0] = fmaf(a.x, b.x, acc[0][0]);
                acc[0][1] = fmaf(a.x, b.y, acc[0][1]);
                acc[0][2] = fmaf(a.x, b.z, acc[0][2]);
                acc[0][3] = fmaf(a.x, b.w, acc[0][3]);
                acc[1][0] = fmaf(a.y, b.x, acc[1][0]);
                acc[1][1] = fmaf(a.y, b.y, acc[1][1]);
                acc[1][2] = fmaf(a.y, b.z, acc[1][2]);
                acc[1][3] = fmaf(a.y, b.w, acc[1][3]);
            }
        }
        // epilogue: gates, c/h update (c in registers across all steps)
        #pragma unroll
        for (int i = 0; i < 2; i++) {
            int b = m0 + ty * 2 + i;
            float gi = acc[i][0] + pg[i][0];
            float gf = acc[i][1] + pg[i][1];
            float gg = acc[i][2] + pg[i][2];
            float go = acc[i][3] + pg[i][3];
            float iv = sigf(gi), fv = sigf(gf);
            float gv = tanhf(gg), ov = sigf(go);
            cst[i] = fv * cst[i] + iv * gv;
            float h = ov * tanhf(cst[i]);
            g_rnn[((size_t)b * Ssz + t) * Dsz + d] = h;
        }
        groupBarrier(mb);
    }
}

// ---------------- attention + aligned + diffusion prep (fused) ----------------
__global__ void attn_diff(const float* __restrict__ W2,
                          const float* __restrict__ b2,
                          const float* __restrict__ noise,
                          const float* __restrict__ temb,
                          const int* __restrict__ tdi)
{
    int s = blockIdx.x;
    int b = blockIdx.y;
    int tid = threadIdx.x;
    const float* ek = g_x + (size_t)b * Ssz * Dsz;
    size_t orow = ((size_t)b * Ssz + s) * Dsz;

    float av;
    if (s == 0) {
        av = ek[tid];
    } else {
        __shared__ float s0[64], s1[64];
        __shared__ float a0s, a1s;
        int sm1 = s - 1;
        if (tid < 64) {
            float f = tanhf(g_featE[b*64 + tid] + g_featW[((size_t)b*Ssz + sm1)*64 + tid]);
            s0[tid] = f * W2[tid];
            s1[tid] = f * W2[64 + tid];
        }
        __syncthreads();
        if (tid == 0) {
            float l0 = b2[0], l1 = b2[1];
            for (int j = 0; j < 64; j++) { l0 += s0[j]; l1 += s1[j]; }
            float m = fmaxf(l0, l1);
            float e0 = expf(l0 - m), e1 = expf(l1 - m);
            float inv = 1.f / (e0 + e1);
            a0s = e0 * inv; a1s = e1 * inv;
        }
        __syncthreads();
        float wv = g_w[((size_t)b * Ssz + sm1) * Dsz + tid];
        av = a0s * ek[tid] + a1s * wv;
    }
    g_aligned[orow + tid] = av;
    float al = g_alpha[b];
    float sa = sqrtf(al), sn = sqrtf(1.f - al);
    g_pre[orow + tid] = av * sa + noise[orow + tid] * sn
                      + temb[(size_t)tdi[b] * Dsz + tid];
}

__global__ void transpose_wdiff(const float* __restrict__ Wdiff)
{
    int n = blockIdx.x, k = threadIdx.x;
    g_WdiffT[n * Dsz + k] = __ldg(Wdiff + k * Dsz + n);
}

// ---------------- fused max-pool + final projections ----------------
__global__ void poolfinal(const float* __restrict__ noise,
                          const float* __restrict__ pn,
                          const float* __restrict__ Wout,
                          const float* __restrict__ bout,
                          float* __restrict__ out)
{
    int b = blockIdx.x, d = threadIdx.x;
    float xm = -INFINITY, gm = -INFINITY;
    for (int s = 0; s < Ssz; s++) {
        size_t i = ((size_t)b * Ssz + s) * Dsz + d;
        xm = fmaxf(xm, g_x[i]);
        float gv = g_aligned[i] + noise[i] - pn[i];
        gm = fmaxf(gm, gv);
    }
    __shared__ float4 red[256];
    red[d] = make_float4(xm * Wout[d], xm * Wout[Dsz + d],
                         gm * Wout[d], gm * Wout[Dsz + d]);
    __syncthreads();
    for (int off = 128; off > 0; off >>= 1) {
        if (d < off) {
            float4 a = red[d], c = red[d + off];
            red[d] = make_float4(a.x + c.x, a.y + c.y, a.z + c.z, a.w + c.w);
        }
        __syncthreads();
    }
    if (d == 0) {
        float4 r = red[0];
        out[b*2 + 0]         = r.x + bout[0];
        out[b*2 + 1]         = r.y + bout[1];
        out[2*Bsz + b*2 + 0] = r.z + bout[0];
        out[2*Bsz + b*2 + 1] = r.w + bout[1];
    }
}

// ---------------- host ----------------
static float* sym(const void* s)
{
    void* p = nullptr;
    cudaGetSymbolAddress(&p, s);
    return (float*)p;
}

extern "C" void kernel_launch(void* const* d_in, const int* in_sizes, int n_in,
                              void* d_out, int out_size)
{
    const int*   seqs   = (const int*)  d_in[0];
    const int*   tdiff  = (const int*)  d_in[5];
    const float* noise  = (const float*)d_in[6];
    const float* emb    = (const float*)d_in[7];
    const float* Wih    = (const float*)d_in[8];
    const float* Whh    = (const float*)d_in[9];
    const float* bih    = (const float*)d_in[10];
    const float* bhh    = (const float*)d_in[11];
    const float* Whk    = (const float*)d_in[12];
    const float* bhk    = (const float*)d_in[13];
    const float* W1     = (const float*)d_in[14];
    const float* b1     = (const float*)d_in[15];
    const float* W2     = (const float*)d_in[16];
    const float* b2     = (const float*)d_in[17];
    const float* Wdiff  = (const float*)d_in[18];
    const float* bdiff  = (const float*)d_in[19];
    const float* temb   = (const float*)d_in[20];
    const float* Wout   = (const float*)d_in[21];
    const float* bout   = (const float*)d_in[22];
    float* out = (float*)d_out;

    float* p_x    = sym(g_x);
    float* p_Gih  = sym(g_Gih);
    float* p_rnn  = sym(g_rnn);
    float* p_w    = sym(g_w);
    float* p_fE   = sym(g_featE);
    float* p_fW   = sym(g_featW);
    float* p_pre  = sym(g_pre);
    float* p_WdT  = sym(g_WdiffT);
    float* p_bsum = sym(g_bsum);

    static bool attr_done = false;
    if (!attr_done) {
        cudaFuncSetAttribute(lstm_fused,
                             cudaFuncAttributeMaxDynamicSharedMemorySize,
                             LSTM_SMEM);
        attr_done = true;
    }

    const int MD = 4 * Dsz;            // 1024
    float* pn_out = out + 4 * Bsz;
    float* nn_out = out + 4 * Bsz + (size_t)Bsz * Ssz * Dsz;

    alpha_kernel<<<1, 256>>>(tdiff);
    bsum_kernel<<<4, 256>>>(bih, bhh);
    embed_kernel<<<Bsz * Ssz, Dsz>>>(seqs, emb);

    // Gih = x @ Wih^T + (bih+bhh)   (12800 x 1024 x 256)
    gemm_nt<<<dim3(MD/64, (Bsz*Ssz)/64), 256>>>(Bsz*Ssz, MD, Dsz,
        p_x, Dsz, Wih, Dsz, p_bsum, p_Gih, MD);

    // fused persistent LSTM (256 thr, group barriers)
    lstm_fused<<<dim3(LSTM_GX, LSTM_GY), 256, LSTM_SMEM>>>(Whh);

    // w = rnn @ Whk^T + bhk   (12800 x 256 x 256)
    gemm_nt<<<dim3(Dsz/64, (Bsz*Ssz)/64), 256>>>(Bsz*Ssz, Dsz, Dsz,
        p_rnn, Dsz, Whk, Dsz, bhk, p_w, Dsz);

    // attention features (N=64)
    gemm_nt<<<dim3(1, Bsz/64), 256>>>(Bsz, 64, Dsz,
        p_x, Ssz * Dsz, W1, 2 * Dsz, b1, p_fE, 64);
    gemm_nt<<<dim3(1, (Bsz*Ssz)/64), 256>>>(Bsz*Ssz, 64, Dsz,
        p_w, Dsz, W1 + Dsz, 2 * Dsz, nullptr, p_fW, 64);

    // attention softmax + aligned + diffusion prep (fused)
    attn_diff<<<dim3(Ssz, Bsz), Dsz>>>(W2, b2, noise, temb, tdiff);

    // predicted_noise = pre @ Wdiff + bdiff
    transpose_wdiff<<<Dsz, Dsz>>>(Wdiff);
    gemm_nt<<<dim3(Dsz/64, (Bsz*Ssz)/64), 256>>>(Bsz*Ssz, Dsz, Dsz,
        p_pre, Dsz, p_WdT, Dsz, bdiff, pn_out, Dsz);

    // fused pool + final
    poolfinal<<<Bsz, Dsz>>>(noise, pn_out, Wout, bout, out);

    // normal_noise passthrough
    cudaMemcpyAsync(nn_out, noise, (size_t)Bsz * Ssz * Dsz * sizeof(float),
                    cudaMemcpyDeviceToDevice);
}

// round 10
// speedup vs baseline: 1.2530x; 1.1663x over previous
#include <cuda_runtime.h>
#include <cuda_bf16.h>
#include <math.h>

#define Bsz 256
#define Ssz 50
#define Csz 40
#define Dsz 256
#define TDIFF 1000

#define LSTM_GX 16
#define LSTM_GY 8
#define LSTM_NBLK (LSTM_GX*LSTM_GY)

// ---------------- scratch ----------------
__device__ float g_x[Bsz*Ssz*Dsz];
__device__ float g_Gih[Bsz*Ssz*4*Dsz];      // x@Wih^T + (bih+bhh)
__device__ float g_hbuf[2][Bsz*Dsz];
__device__ float g_rnn[Bsz*Ssz*Dsz];
__device__ float g_w[Bsz*Ssz*Dsz];
__device__ float g_featE[Bsz*64];
__device__ float g_featW[Bsz*Ssz*64];
__device__ float g_aligned[Bsz*Ssz*Dsz];
__device__ float g_pre[Bsz*Ssz*Dsz];
__device__ float g_alpha[Bsz];
__device__ float g_WdiffT[Dsz*Dsz];
__device__ float g_bsum[4*Dsz];

// bf16 split copies (hi + lo)
__device__ __nv_bfloat16 g_xhi[Bsz*Ssz*Dsz],   g_xlo[Bsz*Ssz*Dsz];
__device__ __nv_bfloat16 g_rnnhi[Bsz*Ssz*Dsz], g_rnnlo[Bsz*Ssz*Dsz];
__device__ __nv_bfloat16 g_prehi[Bsz*Ssz*Dsz], g_prelo[Bsz*Ssz*Dsz];
__device__ __nv_bfloat16 g_Wihhi[4*Dsz*Dsz],   g_Wihlo[4*Dsz*Dsz];
__device__ __nv_bfloat16 g_Whkhi[Dsz*Dsz],     g_Whklo[Dsz*Dsz];
__device__ __nv_bfloat16 g_Wdhi[Dsz*Dsz],      g_Wdlo[Dsz*Dsz];

__device__ unsigned g_barCnt;
__device__ volatile unsigned g_barGen;

// ================= mma.sync bf16 split-GEMM (HMMA, base sm_103) =================
// C[M,N] = A[M,256]·B[N,256]^T + bias via (Ahi+Alo)(Bhi+Blo)^T, 3 terms, f32 accum.
// CTA 128x128, 8 warps (4m x 2n), warp tile 32x64, K chunks of 64.
#define GPAD 72                       // smem row stride in bf16 (conflict-free frags)
#define GTILE (128*GPAD)              // bf16 per tile buffer
#define GM_SMEM (4*GTILE*2)           // 73728 bytes

__device__ __forceinline__ void mma16816(float* c, const unsigned* a, const unsigned* b)
{
    asm volatile(
        "mma.sync.aligned.m16n8k16.row.col.f32.bf16.bf16.f32 "
        "{%0,%1,%2,%3}, {%4,%5,%6,%7}, {%8,%9}, {%0,%1,%2,%3};"
        : "+f"(c[0]), "+f"(c[1]), "+f"(c[2]), "+f"(c[3])
        : "r"(a[0]), "r"(a[1]), "r"(a[2]), "r"(a[3]), "r"(b[0]), "r"(b[1]));
}

__global__ void __launch_bounds__(256, 1)
gemm_mma(const __nv_bfloat16* __restrict__ Ahi, const __nv_bfloat16* __restrict__ Alo,
         const __nv_bfloat16* __restrict__ Bhi, const __nv_bfloat16* __restrict__ Blo,
         const float* __restrict__ bias, float* __restrict__ C, int ldc)
{
    extern __shared__ __nv_bfloat16 sm[];
    __nv_bfloat16* sAh = sm;
    __nv_bfloat16* sAl = sAh + GTILE;
    __nv_bfloat16* sBh = sAl + GTILE;
    __nv_bfloat16* sBl = sBh + GTILE;

    const int tid = threadIdx.x;
    const int w   = tid >> 5;
    const int l   = tid & 31;
    const int wm  = (w >> 1) * 32;     // warp m offset (4 warps in m)
    const int wn  = (w & 1) * 64;      // warp n offset (2 warps in n)
    const int r   = l >> 2;            // groupID
    const int q   = l & 3;             // threadID in group
    const int m0  = blockIdx.y * 128;
    const int n0  = blockIdx.x * 128;

    float acc[2][8][4];
    #pragma unroll
    for (int mi = 0; mi < 2; mi++)
        #pragma unroll
        for (int ni = 0; ni < 8; ni++)
            #pragma unroll
            for (int e = 0; e < 4; e++) acc[mi][ni][e] = 0.f;

    const int srow = tid >> 1;
    const int scol = (tid & 1) * 32;

    for (int kc = 0; kc < 256; kc += 64) {
        // stage 4 tiles of 128x64 bf16 (each thread: 4 x uint4 per tile)
        {
            size_t goffA = (size_t)(m0 + srow) * 256 + kc + scol;
            size_t goffB = (size_t)(n0 + srow) * 256 + kc + scol;
            int soff = srow * GPAD + scol;
            #pragma unroll
            for (int v = 0; v < 4; v++) {
                *(uint4*)(sAh + soff + v*8) = *(const uint4*)(Ahi + goffA + v*8);
                *(uint4*)(sAl + soff + v*8) = *(const uint4*)(Alo + goffA + v*8);
                *(uint4*)(sBh + soff + v*8) = *(const uint4*)(Bhi + goffB + v*8);
                *(uint4*)(sBl + soff + v*8) = *(const uint4*)(Blo + goffB + v*8);
            }
        }
        __syncthreads();

        #pragma unroll
        for (int kk = 0; kk < 4; kk++) {
            const int kb = kk * 16 + 2 * q;
            unsigned ah[2][4], al[2][4], bh[8][2], bl[8][2];
            #pragma unroll
            for (int mi = 0; mi < 2; mi++) {
                int base = (wm + mi*16 + r) * GPAD + kb;
                ah[mi][0] = *(const unsigned*)(sAh + base);
                ah[mi][1] = *(const unsigned*)(sAh + base + 8*GPAD);
                ah[mi][2] = *(const unsigned*)(sAh + base + 8);
                ah[mi][3] = *(const unsigned*)(sAh + base + 8*GPAD + 8);
                al[mi][0] = *(const unsigned*)(sAl + base);
                al[mi][1] = *(const unsigned*)(sAl + base + 8*GPAD);
                al[mi][2] = *(const unsigned*)(sAl + base + 8);
                al[mi][3] = *(const unsigned*)(sAl + base + 8*GPAD + 8);
            }
            #pragma unroll
            for (int ni = 0; ni < 8; ni++) {
                int base = (wn + ni*8 + r) * GPAD + kb;
                bh[ni][0] = *(const unsigned*)(sBh + base);
                bh[ni][1] = *(const unsigned*)(sBh + base + 8);
                bl[ni][0] = *(const unsigned*)(sBl + base);
                bl[ni][1] = *(const unsigned*)(sBl + base + 8);
            }
            #pragma unroll
            for (int mi = 0; mi < 2; mi++)
                #pragma unroll
                for (int ni = 0; ni < 8; ni++) {
                    mma16816(acc[mi][ni], ah[mi], bh[ni]);   // hi*hi
                    mma16816(acc[mi][ni], ah[mi], bl[ni]);   // hi*lo
                    mma16816(acc[mi][ni], al[mi], bh[ni]);   // lo*hi
                }
        }
        __syncthreads();
    }

    // epilogue: + bias, float2 stores
    #pragma unroll
    for (int mi = 0; mi < 2; mi++) {
        int row = m0 + wm + mi*16 + r;
        #pragma unroll
        for (int ni = 0; ni < 8; ni++) {
            int col = n0 + wn + ni*8 + 2*q;
            float b0 = bias[col], b1 = bias[col + 1];
            *(float2*)(C + (size_t)row * ldc + col) =
                make_float2(acc[mi][ni][0] + b0, acc[mi][ni][1] + b1);
            *(float2*)(C + (size_t)(row + 8) * ldc + col) =
                make_float2(acc[mi][ni][2] + b0, acc[mi][ni][3] + b1);
        }
    }
}

// ---------------- split fp32 -> bf16 hi/lo ----------------
__global__ void split_bf16(const float* __restrict__ src,
                           __nv_bfloat16* __restrict__ hi,
                           __nv_bfloat16* __restrict__ lo, int n)
{
    int i = blockIdx.x * 256 + threadIdx.x;
    if (i < n) {
        float x = src[i];
        __nv_bfloat16 h = __float2bfloat16(x);
        hi[i] = h;
        lo[i] = __float2bfloat16(x - __bfloat162float(h));
    }
}

// ================= 64x64 NT GEMM (small feature GEMMs) =================
__global__ void gemm_nt(int M, int N, int K,
                        const float* __restrict__ A, int lda,
                        const float* __restrict__ B, int ldb,
                        const float* __restrict__ bias,
                        float* __restrict__ C, int ldc)
{
    __shared__ float As[16][68];
    __shared__ float Bsh[16][68];
    const int tid = threadIdx.x;
    const int m0 = blockIdx.y * 64;
    const int n0 = blockIdx.x * 64;
    const int tx = tid & 15;
    const int ty = tid >> 4;
    const int lr = tid >> 2;
    const int lc = (tid & 3) * 4;

    float acc[4][4] = {};
    for (int k0 = 0; k0 < K; k0 += 16) {
        float4 a4 = *(const float4*)(A + (size_t)(m0 + lr) * lda + k0 + lc);
        float4 b4 = *(const float4*)(B + (size_t)(n0 + lr) * ldb + k0 + lc);
        As[lc+0][lr] = a4.x; As[lc+1][lr] = a4.y; As[lc+2][lr] = a4.z; As[lc+3][lr] = a4.w;
        Bsh[lc+0][lr] = b4.x; Bsh[lc+1][lr] = b4.y; Bsh[lc+2][lr] = b4.z; Bsh[lc+3][lr] = b4.w;
        __syncthreads();
        #pragma unroll
        for (int k = 0; k < 16; k++) {
            float a[4], b[4];
            #pragma unroll
            for (int i = 0; i < 4; i++) a[i] = As[k][ty*4 + i];
            #pragma unroll
            for (int j = 0; j < 4; j++) b[j] = Bsh[k][tx*4 + j];
            #pragma unroll
            for (int i = 0; i < 4; i++)
                #pragma unroll
                for (int j = 0; j < 4; j++)
                    acc[i][j] = fmaf(a[i], b[j], acc[i][j]);
        }
        __syncthreads();
    }
    #pragma unroll
    for (int i = 0; i < 4; i++) {
        int row = m0 + ty*4 + i;
        #pragma unroll
        for (int j = 0; j < 4; j++) {
            int col = n0 + tx*4 + j;
            float v = acc[i][j];
            if (bias) v += bias[col];
            C[(size_t)row * ldc + col] = v;
        }
    }
}

// ---------------- embedding gather-sum ----------------
__global__ void embed_kernel(const int* __restrict__ seqs,
                             const float* __restrict__ emb)
{
    int bs = blockIdx.x;
    int d  = threadIdx.x;
    __shared__ int idx[Csz];
    if (threadIdx.x < Csz) idx[threadIdx.x] = seqs[bs * Csz + threadIdx.x];
    __syncthreads();
    float acc = 0.f;
    #pragma unroll 8
    for (int c = 0; c < Csz; c++)
        acc += __ldg(emb + (size_t)idx[c] * Dsz + d);
    g_x[(size_t)bs * Dsz + d] = acc;
}

// ---------------- alpha lookup ----------------
__global__ void alpha_kernel(const int* __restrict__ t)
{
    __shared__ float tab[TDIFF];
    if (threadIdx.x == 0) {
        float a = 1.f;
        for (int i = 0; i < TDIFF; i++) {
            float beta = 1e-4f + (0.02f - 1e-4f) * (float)i / (float)(TDIFF - 1);
            a *= (1.f - beta);
            tab[i] = a;
        }
    }
    __syncthreads();
    if (threadIdx.x < Bsz) g_alpha[threadIdx.x] = tab[t[threadIdx.x]];
}

// ---------------- bias sum ----------------
__global__ void bsum_kernel(const float* __restrict__ bih,
                            const float* __restrict__ bhh)
{
    int i = blockIdx.x * 256 + threadIdx.x;
    g_bsum[i] = bih[i] + bhh[i];
}

// ---------------- fused persistent LSTM (proven 963-us config) ----------------
__device__ __forceinline__ float sigf(float x) { return 1.f / (1.f + expf(-x)); }

__device__ __forceinline__ void gridBarrier()
{
    __syncthreads();
    if (threadIdx.x == 0) {
        __threadfence();
        unsigned gen = g_barGen;
        __threadfence();
        if (atomicAdd(&g_barCnt, 1u) == LSTM_NBLK - 1) {
            g_barCnt = 0;
            __threadfence();
            g_barGen = gen + 1;
        } else {
            while (g_barGen == gen) __nanosleep(64);
        }
        __threadfence();
    }
    __syncthreads();
}

#define LSTM_SMEM ((256*68 + 256*36) * (int)sizeof(float))

__global__ void __launch_bounds__(128, 1)
lstm_fused(const float* __restrict__ Whh)
{
    extern __shared__ float sh[];
    float* Bsf = sh;               // [k][j*4+g], stride 68
    float* As  = sh + 256*68;      // [k][m],     stride 36

    const int tid = threadIdx.x;
    const int nb  = blockIdx.x;
    const int mb  = blockIdx.y;
    const int m0  = mb * 32;
    const int tx  = tid & 15;
    const int ty  = tid >> 4;
    const int d   = nb * 16 + tx;

    {
        int r = tid >> 1;
        int g = r & 3, j = r >> 2;
        const float* src = Whh + (size_t)(g * 256 + nb * 16 + j) * 256;
        for (int q = (tid & 1); q < 64; q += 2) {
            float4 v = *(const float4*)(src + q * 4);
            Bsf[(q*4+0)*68 + r] = v.x;
            Bsf[(q*4+1)*68 + r] = v.y;
            Bsf[(q*4+2)*68 + r] = v.z;
            Bsf[(q*4+3)*68 + r] = v.w;
        }
    }
    float cst[4] = {0.f, 0.f, 0.f, 0.f};
    __syncthreads();

    for (int t = 0; t < Ssz; t++) {
        float acc[4][4] = {};
        if (t > 0) {
            const float* hsrc = g_hbuf[(t + 1) & 1] + (size_t)m0 * Dsz;
            int rr = tid >> 2;
            const float* arow = hsrc + (size_t)rr * Dsz;
            for (int q = (tid & 3); q < 64; q += 4) {
                float4 v = *(const float4*)(arow + q * 4);
                As[(q*4+0)*36 + rr] = v.x;
                As[(q*4+1)*36 + rr] = v.y;
                As[(q*4+2)*36 + rr] = v.z;
                As[(q*4+3)*36 + rr] = v.w;
            }
            __syncthreads();
            #pragma unroll 8
            for (int k = 0; k < 256; k++) {
                float4 a = *(const float4*)(As + k * 36 + ty * 4);
                float4 b = *(const float4*)(Bsf + k * 68 + tx * 4);
                float av[4] = {a.x, a.y, a.z, a.w};
                float bv[4] = {b.x, b.y, b.z, b.w};
                #pragma unroll
                for (int i = 0; i < 4; i++)
                    #pragma unroll
                    for (int j = 0; j < 4; j++)
                        acc[i][j] = fmaf(av[i], bv[j], acc[i][j]);
            }
        }
        float* hdst = g_hbuf[t & 1];
        #pragma unroll
        for (int i = 0; i < 4; i++) {
            int b = m0 + ty * 4 + i;
            size_t gbase = ((size_t)b * Ssz + t) * (4 * Dsz) + d;
            float gi = acc[i][0] + g_Gih[gbase];
            float gf = acc[i][1] + g_Gih[gbase + 256];
            float gg = acc[i][2] + g_Gih[gbase + 512];
            float go = acc[i][3] + g_Gih[gbase + 768];
            float iv = sigf(gi), fv = sigf(gf);
            float gv = tanhf(gg), ov = sigf(go);
            cst[i] = fv * cst[i] + iv * gv;
            float h = ov * tanhf(cst[i]);
            hdst[(size_t)b * Dsz + d] = h;
            g_rnn[((size_t)b * Ssz + t) * Dsz + d] = h;
        }
        gridBarrier();
    }
}

// ---------------- attention + aligned + diffusion prep (fused) ----------------
__global__ void attn_diff(const float* __restrict__ W2,
                          const float* __restrict__ b2,
                          const float* __restrict__ noise,
                          const float* __restrict__ temb,
                          const int* __restrict__ tdi)
{
    int s = blockIdx.x;
    int b = blockIdx.y;
    int tid = threadIdx.x;
    const float* ek = g_x + (size_t)b * Ssz * Dsz;
    size_t orow = ((size_t)b * Ssz + s) * Dsz;

    float av;
    if (s == 0) {
        av = ek[tid];
    } else {
        __shared__ float s0[64], s1[64];
        __shared__ float a0s, a1s;
        int sm1 = s - 1;
        if (tid < 64) {
            float f = tanhf(g_featE[b*64 + tid] + g_featW[((size_t)b*Ssz + sm1)*64 + tid]);
            s0[tid] = f * W2[tid];
            s1[tid] = f * W2[64 + tid];
        }
        __syncthreads();
        if (tid == 0) {
            float l0 = b2[0], l1 = b2[1];
            for (int j = 0; j < 64; j++) { l0 += s0[j]; l1 += s1[j]; }
            float m = fmaxf(l0, l1);
            float e0 = expf(l0 - m), e1 = expf(l1 - m);
            float inv = 1.f / (e0 + e1);
            a0s = e0 * inv; a1s = e1 * inv;
        }
        __syncthreads();
        float wv = g_w[((size_t)b * Ssz + sm1) * Dsz + tid];
        av = a0s * ek[tid] + a1s * wv;
    }
    g_aligned[orow + tid] = av;
    float al = g_alpha[b];
    float sa = sqrtf(al), sn = sqrtf(1.f - al);
    g_pre[orow + tid] = av * sa + noise[orow + tid] * sn
                      + temb[(size_t)tdi[b] * Dsz + tid];
}

__global__ void transpose_wdiff(const float* __restrict__ Wdiff)
{
    int n = blockIdx.x, k = threadIdx.x;
    g_WdiffT[n * Dsz + k] = __ldg(Wdiff + k * Dsz + n);
}

// ---------------- fused max-pool + final projections ----------------
__global__ void poolfinal(const float* __restrict__ noise,
                          const float* __restrict__ pn,
                          const float* __restrict__ Wout,
                          const float* __restrict__ bout,
                          float* __restrict__ out)
{
    int b = blockIdx.x, d = threadIdx.x;
    float xm = -INFINITY, gm = -INFINITY;
    for (int s = 0; s < Ssz; s++) {
        size_t i = ((size_t)b * Ssz + s) * Dsz + d;
        xm = fmaxf(xm, g_x[i]);
        float gv = g_aligned[i] + noise[i] - pn[i];
        gm = fmaxf(gm, gv);
    }
    __shared__ float4 red[256];
    red[d] = make_float4(xm * Wout[d], xm * Wout[Dsz + d],
                         gm * Wout[d], gm * Wout[Dsz + d]);
    __syncthreads();
    for (int off = 128; off > 0; off >>= 1) {
        if (d < off) {
            float4 a = red[d], c = red[d + off];
            red[d] = make_float4(a.x + c.x, a.y + c.y, a.z + c.z, a.w + c.w);
        }
        __syncthreads();
    }
    if (d == 0) {
        float4 r = red[0];
        out[b*2 + 0]         = r.x + bout[0];
        out[b*2 + 1]         = r.y + bout[1];
        out[2*Bsz + b*2 + 0] = r.z + bout[0];
        out[2*Bsz + b*2 + 1] = r.w + bout[1];
    }
}

// ---------------- host ----------------
static float* symf(const void* s)
{
    void* p = nullptr;
    cudaGetSymbolAddress(&p, s);
    return (float*)p;
}
static __nv_bfloat16* symb(const void* s)
{
    void* p = nullptr;
    cudaGetSymbolAddress(&p, s);
    return (__nv_bfloat16*)p;
}

extern "C" void kernel_launch(void* const* d_in, const int* in_sizes, int n_in,
                              void* d_out, int out_size)
{
    const int*   seqs   = (const int*)  d_in[0];
    const int*   tdiff  = (const int*)  d_in[5];
    const float* noise  = (const float*)d_in[6];
    const float* emb    = (const float*)d_in[7];
    const float* Wih    = (const float*)d_in[8];
    const float* Whh    = (const float*)d_in[9];
    const float* bih    = (const float*)d_in[10];
    const float* bhh    = (const float*)d_in[11];
    const float* Whk    = (const float*)d_in[12];
    const float* bhk    = (const float*)d_in[13];
    const float* W1     = (const float*)d_in[14];
    const float* b1     = (const float*)d_in[15];
    const float* W2     = (const float*)d_in[16];
    const float* b2     = (const float*)d_in[17];
    const float* Wdiff  = (const float*)d_in[18];
    const float* bdiff  = (const float*)d_in[19];
    const float* temb   = (const float*)d_in[20];
    const float* Wout   = (const float*)d_in[21];
    const float* bout   = (const float*)d_in[22];
    float* out = (float*)d_out;

    float* p_x    = symf(g_x);
    float* p_Gih  = symf(g_Gih);
    float* p_rnn  = symf(g_rnn);
    float* p_w    = symf(g_w);
    float* p_fE   = symf(g_featE);
    float* p_fW   = symf(g_featW);
    float* p_pre  = symf(g_pre);
    float* p_WdT  = symf(g_WdiffT);
    float* p_bsum = symf(g_bsum);

    __nv_bfloat16* p_xhi   = symb(g_xhi);
    __nv_bfloat16* p_xlo   = symb(g_xlo);
    __nv_bfloat16* p_rhi   = symb(g_rnnhi);
    __nv_bfloat16* p_rlo   = symb(g_rnnlo);
    __nv_bfloat16* p_phi   = symb(g_prehi);
    __nv_bfloat16* p_plo   = symb(g_prelo);
    __nv_bfloat16* p_Wihhi = symb(g_Wihhi);
    __nv_bfloat16* p_Wihlo = symb(g_Wihlo);
    __nv_bfloat16* p_Whkhi = symb(g_Whkhi);
    __nv_bfloat16* p_Whklo = symb(g_Whklo);
    __nv_bfloat16* p_Wdhi  = symb(g_Wdhi);
    __nv_bfloat16* p_Wdlo  = symb(g_Wdlo);

    static bool attr_done = false;
    if (!attr_done) {
        cudaFuncSetAttribute(lstm_fused,
                             cudaFuncAttributeMaxDynamicSharedMemorySize, LSTM_SMEM);
        cudaFuncSetAttribute(gemm_mma,
                             cudaFuncAttributeMaxDynamicSharedMemorySize, GM_SMEM);
        attr_done = true;
    }

    const int BSD = Bsz * Ssz * Dsz;     // 3,276,800
    float* pn_out = out + 4 * Bsz;
    float* nn_out = out + 4 * Bsz + (size_t)BSD;

    alpha_kernel<<<1, 256>>>(tdiff);
    bsum_kernel<<<4, 256>>>(bih, bhh);

    // weight splits
    split_bf16<<<(4*Dsz*Dsz)/256, 256>>>(Wih, p_Wihhi, p_Wihlo, 4*Dsz*Dsz);
    split_bf16<<<(Dsz*Dsz)/256, 256>>>(Whk, p_Whkhi, p_Whklo, Dsz*Dsz);
    transpose_wdiff<<<Dsz, Dsz>>>(Wdiff);
    split_bf16<<<(Dsz*Dsz)/256, 256>>>(p_WdT, p_Wdhi, p_Wdlo, Dsz*Dsz);

    // embedding + split x
    embed_kernel<<<Bsz * Ssz, Dsz>>>(seqs, emb);
    split_bf16<<<BSD/256, 256>>>(p_x, p_xhi, p_xlo, BSD);

    // Gih = x @ Wih^T + (bih+bhh)   (12800 x 1024, HMMA)
    gemm_mma<<<dim3(8, 100), 256, GM_SMEM>>>(p_xhi, p_xlo, p_Wihhi, p_Wihlo,
                                             p_bsum, p_Gih, 4*Dsz);

    // fused persistent LSTM
    lstm_fused<<<dim3(LSTM_GX, LSTM_GY), 128, LSTM_SMEM>>>(Whh);

    // w = rnn @ Whk^T + bhk   (12800 x 256, HMMA)
    split_bf16<<<BSD/256, 256>>>(p_rnn, p_rhi, p_rlo, BSD);
    gemm_mma<<<dim3(2, 100), 256, GM_SMEM>>>(p_rhi, p_rlo, p_Whkhi, p_Whklo,
                                             bhk, p_w, Dsz);

    // attention features (N=64, scalar GEMM)
    gemm_nt<<<dim3(1, Bsz/64), 256>>>(Bsz, 64, Dsz,
        p_x, Ssz * Dsz, W1, 2 * Dsz, b1, p_fE, 64);
    gemm_nt<<<dim3(1, (Bsz*Ssz)/64), 256>>>(Bsz*Ssz, 64, Dsz,
        p_w, Dsz, W1 + Dsz, 2 * Dsz, nullptr, p_fW, 64);

    // attention softmax + aligned + diffusion prep
    attn_diff<<<dim3(Ssz, Bsz), Dsz>>>(W2, b2, noise, temb, tdiff);

    // predicted_noise = pre @ Wdiff + bdiff   (12800 x 256, HMMA)
    split_bf16<<<BSD/256, 256>>>(p_pre, p_phi, p_plo, BSD);
    gemm_mma<<<dim3(2, 100), 256, GM_SMEM>>>(p_phi, p_plo, p_Wdhi, p_Wdlo,
                                             bdiff, pn_out, Dsz);

    // fused pool + final
    poolfinal<<<Bsz, Dsz>>>(noise, pn_out, Wout, bout, out);

    // normal_noise passthrough
    cudaMemcpyAsync(nn_out, noise, (size_t)BSD * sizeof(float),
                    cudaMemcpyDeviceToDevice);
}